// round 12
// baseline (speedup 1.0000x reference)
#include <cuda_runtime.h>
#include <cuda_bf16.h>

#define NCTA 128
#define NT 640
#define TT 1024
#define BB 128
#define HH 256

__device__ float g_h[2][BB * HH];
__device__ float g_u[BB * HH];
__device__ unsigned g_flagH[4][32][8];
__device__ unsigned g_flagU[4][32][8];

__device__ __forceinline__ float4 ldcg4(const float4* p) {
    float4 v;
    asm volatile("ld.global.cg.v4.f32 {%0,%1,%2,%3}, [%4];"
                 : "=f"(v.x), "=f"(v.y), "=f"(v.z), "=f"(v.w) : "l"(p));
    return v;
}
__device__ __forceinline__ float ldcg1(const float* p) {
    float v;
    asm volatile("ld.global.cg.f32 %0, [%1];" : "=f"(v) : "l"(p));
    return v;
}
__device__ __forceinline__ unsigned ldrelax(const unsigned* p) {
    unsigned v;
    asm volatile("ld.relaxed.gpu.global.u32 %0, [%1];" : "=r"(v) : "l"(p) : "memory");
    return v;
}
__device__ __forceinline__ void fence_gpu() {
    asm volatile("fence.acq_rel.gpu;" ::: "memory");
}
__device__ __forceinline__ float fast_tanh(float x) {
    float ax = fabsf(x);
    float e = __expf(2.0f * ax);
    float r = 1.0f - 2.0f / (e + 1.0f);
    return copysignf(r, x);
}
__device__ __forceinline__ float fast_sigmoid(float x) {
    return 1.0f / (1.0f + __expf(-x));
}

// SMEM layout (floats)
#define OFF_W1S 0                     // [256][40]
#define OFF_W2S 10240                 // [256][16]
#define OFF_S1  14336                 // [4][40][33]
#define OFF_S2  19616                 // [8][16][33]
#define OFF_AMP 23840                 // [32]
#define OFF_COS 23872
#define OFF_SIN 23904
#define OFF_W0  23936                 // [3][8]
#define OFF_B1  23960                 // [3][8]
#define OFF_BZ  23984                 // [8]
#define OFF_BH  23992                 // [8]
#define OFF_WOF 24000                 // [256][2]
#define OFF_BO  24512                 // [2]
#define OFF_BASE 24514                // [2] epoch bases (as uint bits)
#define SMEM_FLOATS 24516
#define SMEM_BYTES (SMEM_FLOATS * 4)

__global__ void __launch_bounds__(NT, 1) pgjanet_kernel(
    const float* __restrict__ x,   const float* __restrict__ h0,
    const float* __restrict__ Wa,  const float* __restrict__ ba,
    const float* __restrict__ Wp1, const float* __restrict__ bp1,
    const float* __restrict__ Wp2, const float* __restrict__ bp2,
    const float* __restrict__ Wz,  const float* __restrict__ bz,
    const float* __restrict__ Wh,  const float* __restrict__ bh,
    const float* __restrict__ Wo,  const float* __restrict__ bo,
    float* __restrict__ out)
{
    extern __shared__ float sm[];
    float* W1s = sm + OFF_W1S;
    float* W2s = sm + OFF_W2S;
    float* S1  = sm + OFF_S1;
    float* S2  = sm + OFF_S2;
    float* s_amp = sm + OFF_AMP;
    float* s_cos = sm + OFF_COS;
    float* s_sin = sm + OFF_SIN;
    float* s_w0  = sm + OFF_W0;
    float* s_b1  = sm + OFF_B1;
    float* s_bz  = sm + OFF_BZ;
    float* s_bh  = sm + OFF_BH;
    float* s_Wo  = sm + OFF_WOF;
    float* s_bo  = sm + OFF_BO;
    unsigned* s_base = (unsigned*)(sm + OFF_BASE);

    const int tid  = threadIdx.x;
    const int lane = tid & 31;
    const int wid  = tid >> 5;
    const int nj = blockIdx.x & 31;   // column slice (8 cols)
    const int mi = blockIdx.x >> 5;   // row group (32 rows)
    const int j0 = nj * 8;
    const int r0 = mi * 32;

    unsigned* flH = &g_flagH[mi][0][0];
    unsigned* flU = &g_flagU[mi][0][0];

    // Epoch bases: read own flags (only this CTA writes them), publish to ALL
    // warps via SMEM (an earlier __shfl_sync-based broadcast only reached
    // warp 0 — the replay-nondeterminism bug).
    if (tid == 0) {
        s_base[0] = ldrelax(flH + nj * 8);
        s_base[1] = ldrelax(flU + nj * 8);
    }

    // ---- preload loop-invariant weights into SMEM ----
    for (int idx = tid; idx < 256 * 40; idx += NT) {
        int k = idx / 40, nn = idx % 40;
        int mat = nn >> 3, j = j0 + (nn & 7);
        float v;
        if      (mat == 0) v = Wa [(1 + k) * HH + j];
        else if (mat == 1) v = Wp1[(1 + k) * HH + j];
        else if (mat == 2) v = Wp2[(1 + k) * HH + j];
        else if (mat == 3) v = Wz [(HH + k) * HH + j];
        else               v = Wh [(HH + k) * HH + j];
        W1s[k * 40 + nn] = v;
    }
    for (int idx = tid; idx < 256 * 16; idx += NT) {
        int k = idx / 16, nn = idx % 16;
        int j = j0 + (nn & 7);
        W2s[k * 16 + nn] = (nn < 8) ? Wz[k * HH + j] : Wh[k * HH + j];
    }
    for (int idx = tid; idx < 512; idx += NT) s_Wo[idx] = Wo[idx];
    if (tid < 8) {
        int j = j0 + tid;
        s_w0[tid]      = Wa [j];  s_w0[8 + tid]  = Wp1[j];  s_w0[16 + tid] = Wp2[j];
        s_b1[tid]      = ba [j];  s_b1[8 + tid]  = bp1[j];  s_b1[16 + tid] = bp2[j];
        s_bz[tid] = bz[j];        s_bh[tid] = bh[j];
    }
    if (tid == 0) { s_bo[0] = bo[0]; s_bo[1] = bo[1]; }
    __syncthreads();

    const unsigned baseH = s_base[0];
    const unsigned baseU = s_base[1];

    for (int t = 0; t < TT; ++t) {
        // ---- warp 0: per-row x inputs (independent of flags) ----
        if (tid < 32) {
            const float* xp = x + (((r0 + tid) * TT) + t) * 2;
            float amp = __ldg(xp), ph = __ldg(xp + 1);
            s_amp[tid] = amp;
            float sv, cv; sincosf(ph, &sv, &cv);
            s_sin[tid] = sv; s_cos[tid] = cv;
        }

        // ---- GEMM1: 20 warps = 5 cg (8 cols) x 4 kq; stream h from L2 ----
        {
            int cg = wid % 5, kq = wid / 5;
            if (t > 0) {
                const unsigned* p = flH + (8 * kq + (lane & 7)) * 8;
                unsigned v;
                do { v = ldrelax(p); }
                while (__any_sync(0xffffffffu, (v - baseH) < (unsigned)t));
                fence_gpu();
            }
            const float* hrow = ((t == 0) ? h0 : g_h[t & 1]) + (r0 + lane) * HH;
            const float4* hp = (const float4*)hrow + kq * 16;
            float4 hb[4];
            hb[0] = ldcg4(hp + 0); hb[1] = ldcg4(hp + 1);
            hb[2] = ldcg4(hp + 2); hb[3] = ldcg4(hp + 3);
            float a0 = 0.f, a1 = 0.f, a2 = 0.f, a3 = 0.f;
            float a4 = 0.f, a5 = 0.f, a6 = 0.f, a7 = 0.f;
            const float* wp = W1s + cg * 8;
            #pragma unroll
            for (int mm = 0; mm < 16; ++mm) {
                float4 hv = hb[mm & 3];
                if (mm < 12) hb[mm & 3] = ldcg4(hp + mm + 4);
                int m = kq * 16 + mm;
                #pragma unroll
                for (int d = 0; d < 4; ++d) {
                    float hk = (d == 0) ? hv.x : (d == 1) ? hv.y : (d == 2) ? hv.z : hv.w;
                    float4 w0 = *(const float4*)&wp[(4 * m + d) * 40];
                    float4 w1 = *(const float4*)&wp[(4 * m + d) * 40 + 4];
                    a0 += hk * w0.x; a1 += hk * w0.y; a2 += hk * w0.z; a3 += hk * w0.w;
                    a4 += hk * w1.x; a5 += hk * w1.y; a6 += hk * w1.z; a7 += hk * w1.w;
                }
            }
            float* s = S1 + kq * 1320 + (cg * 8) * 33 + lane;
            s[0]   = a0; s[33]  = a1; s[66]  = a2; s[99]  = a3;
            s[132] = a4; s[165] = a5; s[198] = a6; s[231] = a7;
        }
        __syncthreads();

        // ---- epilogue 1: a, p1, p2 -> u ----
        if (tid < 256) {
            int jj = tid & 7, r = tid >> 3;
            float sa = 0.f, sp1 = 0.f, sp2 = 0.f;
            #pragma unroll
            for (int q = 0; q < 4; ++q) {
                sa  += S1[q * 1320 + (0  + jj) * 33 + r];
                sp1 += S1[q * 1320 + (8  + jj) * 33 + r];
                sp2 += S1[q * 1320 + (16 + jj) * 33 + r];
            }
            float a  = fast_tanh(sa  + s_amp[r] * s_w0[jj]      + s_b1[jj]);
            float p1 = fast_tanh(sp1 + s_cos[r] * s_w0[8 + jj]  + s_b1[8 + jj]);
            float p2 = fast_tanh(sp2 + s_sin[r] * s_w0[16 + jj] + s_b1[16 + jj]);
            g_u[(r0 + r) * HH + j0 + jj] =
                a * p1 * p2 * (1.f - a) * (1.f - p1) * (1.f - p2);
        }
        __syncthreads();
        if (tid == 0) {
            fence_gpu();
            asm volatile("st.relaxed.gpu.global.u32 [%0], %1;"
                         :: "l"(flU + nj * 8), "r"(baseU + (unsigned)(t + 1)) : "memory");
        }

        // ---- GEMM2: warps 0-15 = 2 cg2 (8 cols) x 8 ke; stream u from L2 ----
        if (wid < 16) {
            int cg2 = wid & 1, ke = wid >> 1;
            {
                const unsigned* p = flU + (4 * ke + (lane & 3)) * 8;
                unsigned v;
                do { v = ldrelax(p); }
                while (__any_sync(0xffffffffu, (v - baseU) < (unsigned)(t + 1)));
                fence_gpu();
            }
            const float4* up = (const float4*)(g_u + (r0 + lane) * HH) + ke * 8;
            float4 ub[8];
            #pragma unroll
            for (int q = 0; q < 8; ++q) ub[q] = ldcg4(up + q);
            float a0 = 0.f, a1 = 0.f, a2 = 0.f, a3 = 0.f;
            float a4 = 0.f, a5 = 0.f, a6 = 0.f, a7 = 0.f;
            const float* wp = W2s + cg2 * 8;
            #pragma unroll
            for (int mm = 0; mm < 8; ++mm) {
                float4 uv = ub[mm];
                int m = ke * 8 + mm;
                #pragma unroll
                for (int d = 0; d < 4; ++d) {
                    float uk = (d == 0) ? uv.x : (d == 1) ? uv.y : (d == 2) ? uv.z : uv.w;
                    float4 w0 = *(const float4*)&wp[(4 * m + d) * 16];
                    float4 w1 = *(const float4*)&wp[(4 * m + d) * 16 + 4];
                    a0 += uk * w0.x; a1 += uk * w0.y; a2 += uk * w0.z; a3 += uk * w0.w;
                    a4 += uk * w1.x; a5 += uk * w1.y; a6 += uk * w1.z; a7 += uk * w1.w;
                }
            }
            float* s = S2 + ke * 528 + (cg2 * 8) * 33 + lane;
            s[0]   = a0; s[33]  = a1; s[66]  = a2; s[99]  = a3;
            s[132] = a4; s[165] = a5; s[198] = a6; s[231] = a7;
        } else if (nj == 0 && t >= 1) {
            // warps 16-19: output row t-1 from g_h[t&1] (= h(t-1))
            const float* hb = g_h[t & 1];
            #pragma unroll
            for (int it = 0; it < 2; ++it) {
                int item = it * 128 + (wid - 16) * 32 + lane;
                int r = item >> 3, kk = item & 7;
                float o0 = 0.f, o1 = 0.f;
                #pragma unroll
                for (int q = 0; q < 8; ++q) {
                    float4 hv = ldcg4((const float4*)(hb + (r0 + r) * HH + kk * 32) + q);
                    int k = kk * 32 + q * 4;
                    o0 += hv.x * s_Wo[k * 2]     + hv.y * s_Wo[k * 2 + 2]
                        + hv.z * s_Wo[k * 2 + 4] + hv.w * s_Wo[k * 2 + 6];
                    o1 += hv.x * s_Wo[k * 2 + 1] + hv.y * s_Wo[k * 2 + 3]
                        + hv.z * s_Wo[k * 2 + 5] + hv.w * s_Wo[k * 2 + 7];
                }
                o0 += __shfl_xor_sync(0xffffffffu, o0, 1);
                o0 += __shfl_xor_sync(0xffffffffu, o0, 2);
                o0 += __shfl_xor_sync(0xffffffffu, o0, 4);
                o1 += __shfl_xor_sync(0xffffffffu, o1, 1);
                o1 += __shfl_xor_sync(0xffffffffu, o1, 2);
                o1 += __shfl_xor_sync(0xffffffffu, o1, 4);
                if (kk == 0) {
                    float* op = out + (((r0 + r) * TT) + (t - 1)) * 2;
                    op[0] = o0 + s_bo[0];
                    op[1] = o1 + s_bo[1];
                }
            }
        }
        __syncthreads();

        // ---- epilogue 2: z, h_cand, h_new -> g_h[(t+1)&1] ----
        if (tid < 256) {
            int jj = tid & 7, r = tid >> 3;
            int j = j0 + jj;
            float zp = s_bz[jj], hp = s_bh[jj];
            #pragma unroll
            for (int e = 0; e < 8; ++e) {
                zp += S2[e * 528 + jj * 33 + r];
                hp += S2[e * 528 + (8 + jj) * 33 + r];
            }
            #pragma unroll
            for (int q = 0; q < 4; ++q) {
                zp += S1[q * 1320 + (24 + jj) * 33 + r];
                hp += S1[q * 1320 + (32 + jj) * 33 + r];
            }
            float z  = fast_sigmoid(zp);
            float hc = fast_tanh(hp);
            const float* hsrc = (t == 0) ? h0 : g_h[t & 1];
            float hold = ldcg1(&hsrc[(r0 + r) * HH + j]);
            float hn = z * hold + (1.f - z) * hc;
            g_h[(t + 1) & 1][(r0 + r) * HH + j] = hn;
            if (t == TT - 1)
                out[BB * TT * 2 + (r0 + r) * HH + j] = hn;
        }
        __syncthreads();
        if (tid == 0) {
            fence_gpu();
            asm volatile("st.relaxed.gpu.global.u32 [%0], %1;"
                         :: "l"(flH + nj * 8), "r"(baseH + (unsigned)(t + 1)) : "memory");
        }
    }

    // ---- final output row t=1023 from g_h[TT&1] (= h(1023)) ----
    if (nj == 0) {
        if (tid < 32) {
            const unsigned* p = flH + lane * 8;
            unsigned v;
            do { v = ldrelax(p); }
            while (__any_sync(0xffffffffu, (v - baseH) < (unsigned)TT));
            fence_gpu();
        }
        __syncthreads();
        if (tid < 256) {
            int r = tid >> 3, kk = tid & 7;
            const float* hb = g_h[TT & 1];
            float o0 = 0.f, o1 = 0.f;
            #pragma unroll
            for (int q = 0; q < 8; ++q) {
                float4 hv = ldcg4((const float4*)(hb + (r0 + r) * HH + kk * 32) + q);
                int k = kk * 32 + q * 4;
                o0 += hv.x * s_Wo[k * 2]     + hv.y * s_Wo[k * 2 + 2]
                    + hv.z * s_Wo[k * 2 + 4] + hv.w * s_Wo[k * 2 + 6];
                o1 += hv.x * s_Wo[k * 2 + 1] + hv.y * s_Wo[k * 2 + 3]
                    + hv.z * s_Wo[k * 2 + 5] + hv.w * s_Wo[k * 2 + 7];
            }
            o0 += __shfl_xor_sync(0xffffffffu, o0, 1);
            o0 += __shfl_xor_sync(0xffffffffu, o0, 2);
            o0 += __shfl_xor_sync(0xffffffffu, o0, 4);
            o1 += __shfl_xor_sync(0xffffffffu, o1, 1);
            o1 += __shfl_xor_sync(0xffffffffu, o1, 2);
            o1 += __shfl_xor_sync(0xffffffffu, o1, 4);
            if (kk == 0) {
                float* op = out + (((r0 + r) * TT) + (TT - 1)) * 2;
                op[0] = o0 + s_bo[0];
                op[1] = o1 + s_bo[1];
            }
        }
    }
}

extern "C" void kernel_launch(void* const* d_in, const int* in_sizes, int n_in,
                              void* d_out, int out_size) {
    const float* x   = (const float*)d_in[0];
    const float* h0  = (const float*)d_in[1];
    const float* Wa  = (const float*)d_in[2];
    const float* ba  = (const float*)d_in[3];
    const float* Wp1 = (const float*)d_in[4];
    const float* bp1 = (const float*)d_in[5];
    const float* Wp2 = (const float*)d_in[6];
    const float* bp2 = (const float*)d_in[7];
    const float* Wz  = (const float*)d_in[8];
    const float* bz  = (const float*)d_in[9];
    const float* Wh  = (const float*)d_in[10];
    const float* bh  = (const float*)d_in[11];
    const float* Wo  = (const float*)d_in[12];
    const float* bo  = (const float*)d_in[13];
    float* out = (float*)d_out;

    cudaFuncSetAttribute(pgjanet_kernel,
                         cudaFuncAttributeMaxDynamicSharedMemorySize, SMEM_BYTES);
    pgjanet_kernel<<<NCTA, NT, SMEM_BYTES>>>(
        x, h0, Wa, ba, Wp1, bp1, Wp2, bp2, Wz, bz, Wh, bh, Wo, bo, out);
}

// round 13
// speedup vs baseline: 1.2632x; 1.2632x over previous
#include <cuda_runtime.h>
#include <cuda_bf16.h>

#define NCTA 256
#define NT 320
#define TT 1024
#define BB 128
#define HH 256

__device__ float g_h[BB * HH];
__device__ float g_u[BB * HH];
__device__ unsigned g_flags[8][32][8];

__device__ __forceinline__ float4 ldcg4(const float4* p) {
    float4 v;
    asm volatile("ld.global.cg.v4.f32 {%0,%1,%2,%3}, [%4];"
                 : "=f"(v.x), "=f"(v.y), "=f"(v.z), "=f"(v.w) : "l"(p));
    return v;
}
__device__ __forceinline__ float ldcg1(const float* p) {
    float v;
    asm volatile("ld.global.cg.f32 %0, [%1];" : "=f"(v) : "l"(p));
    return v;
}
__device__ __forceinline__ unsigned ldrelax(const unsigned* p) {
    unsigned v;
    asm volatile("ld.relaxed.gpu.global.u32 %0, [%1];" : "=r"(v) : "l"(p) : "memory");
    return v;
}
__device__ __forceinline__ float fast_tanh(float x) {
    float ax = fabsf(x);
    float e = __expf(2.0f * ax);
    float r = 1.0f - 2.0f / (e + 1.0f);
    return copysignf(r, x);
}
__device__ __forceinline__ float fast_sigmoid(float x) {
    return 1.0f / (1.0f + __expf(-x));
}

// Row-group barrier: 32 CTAs (same mi), flag store + 32-lane poll in warp 0.
__device__ __forceinline__ void group_bar(unsigned* fl, int nj, unsigned base, unsigned ep) {
    __syncthreads();
    if (threadIdx.x < 32) {
        if (threadIdx.x == 0) {
            asm volatile("fence.acq_rel.gpu;" ::: "memory");
            asm volatile("st.relaxed.gpu.global.u32 [%0], %1;"
                         :: "l"(fl + nj * 8), "r"(base + ep) : "memory");
        }
        unsigned v;
        unsigned* p = fl + threadIdx.x * 8;
        do { v = ldrelax(p); }
        while (__any_sync(0xffffffffu, (v - base) < ep));
        asm volatile("fence.acq_rel.gpu;" ::: "memory");
    }
    __syncthreads();
}

// SMEM layout (floats), total 25602 floats = 102,408 B  (x2 CTAs = 205KB/SM)
#define OFF_W1S 0                     // [256][40]
#define OFF_W2S 10240                 // [256][16]
#define OFF_H4S 14336                 // [64][16][4]
#define OFF_U4S 18432                 // [64][16][4]
#define OFF_S1  22528                 // [2][40][17]  k-half partials
#define OFF_S2  23888                 // [4][16][17]  k-quarter partials
#define OFF_AMP 24976                 // [16]
#define OFF_COS 24992
#define OFF_SIN 25008
#define OFF_W0  25024                 // [3][8]
#define OFF_B1  25048                 // [3][8]
#define OFF_BZ  25072                 // [8]
#define OFF_BH  25080                 // [8]
#define OFF_WOF 25088                 // [256][2]
#define OFF_BO  25600                 // [2]
#define SMEM_FLOATS 25602
#define SMEM_BYTES (SMEM_FLOATS * 4)

__global__ void __launch_bounds__(NT, 2) pgjanet_kernel(
    const float* __restrict__ x,   const float* __restrict__ h0,
    const float* __restrict__ Wa,  const float* __restrict__ ba,
    const float* __restrict__ Wp1, const float* __restrict__ bp1,
    const float* __restrict__ Wp2, const float* __restrict__ bp2,
    const float* __restrict__ Wz,  const float* __restrict__ bz,
    const float* __restrict__ Wh,  const float* __restrict__ bh,
    const float* __restrict__ Wo,  const float* __restrict__ bo,
    float* __restrict__ out)
{
    extern __shared__ float sm[];
    float* W1s = sm + OFF_W1S;
    float* W2s = sm + OFF_W2S;
    float* h4s = sm + OFF_H4S;
    float* u4s = sm + OFF_U4S;
    float* S1  = sm + OFF_S1;
    float* S2  = sm + OFF_S2;
    float* s_amp = sm + OFF_AMP;
    float* s_cos = sm + OFF_COS;
    float* s_sin = sm + OFF_SIN;
    float* s_w0  = sm + OFF_W0;
    float* s_b1  = sm + OFF_B1;
    float* s_bz  = sm + OFF_BZ;
    float* s_bh  = sm + OFF_BH;
    float* s_Wo  = sm + OFF_WOF;
    float* s_bo  = sm + OFF_BO;

    const int tid  = threadIdx.x;
    const int lane = tid & 31;
    const int wid  = tid >> 5;
    const int nj = blockIdx.x & 31;   // column slice (8 cols)
    const int mi = blockIdx.x >> 5;   // row group (16 rows), 8 groups
    const int j0 = nj * 8;
    const int r0 = mi * 16;

    unsigned* fl = &g_flags[mi][0][0];

    unsigned base = 0;
    if (tid < 32)
        base = ldrelax(fl + nj * 8);   // own flag; only warp 0 uses base

    // ---- preload loop-invariant weights into SMEM ----
    for (int idx = tid; idx < 256 * 40; idx += NT) {
        int k = idx / 40, nn = idx % 40;
        int mat = nn >> 3, j = j0 + (nn & 7);
        float v;
        if      (mat == 0) v = Wa [(1 + k) * HH + j];
        else if (mat == 1) v = Wp1[(1 + k) * HH + j];
        else if (mat == 2) v = Wp2[(1 + k) * HH + j];
        else if (mat == 3) v = Wz [(HH + k) * HH + j];
        else               v = Wh [(HH + k) * HH + j];
        W1s[k * 40 + nn] = v;
    }
    for (int idx = tid; idx < 256 * 16; idx += NT) {
        int k = idx / 16, nn = idx % 16;
        int j = j0 + (nn & 7);
        W2s[k * 16 + nn] = (nn < 8) ? Wz[k * HH + j] : Wh[k * HH + j];
    }
    for (int idx = tid; idx < 512; idx += NT) s_Wo[idx] = Wo[idx];
    if (tid < 8) {
        int j = j0 + tid;
        s_w0[tid]      = Wa [j];  s_w0[8 + tid]  = Wp1[j];  s_w0[16 + tid] = Wp2[j];
        s_b1[tid]      = ba [j];  s_b1[8 + tid]  = bp1[j];  s_b1[16 + tid] = bp2[j];
        s_bz[tid] = bz[j];        s_bh[tid] = bh[j];
    }
    if (tid == 0) { s_bo[0] = bo[0]; s_bo[1] = bo[1]; }

    unsigned ep = 0;

    for (int t = 0; t < TT; ++t) {
        // ---- stage 1: load 16-row h tile into SMEM ([kc][row][4]) ----
        const float* hsrc = (t == 0) ? h0 : g_h;
        for (int idx = tid; idx < 16 * 64; idx += NT) {
            int r = idx >> 6, kc = idx & 63;
            float4 v = ldcg4((const float4*)(hsrc + (r0 + r) * HH) + kc);
            *(float4*)&h4s[(kc * 16 + r) * 4] = v;
        }
        if (tid < 16) {
            const float* xp = x + (((r0 + tid) * TT) + t) * 2;
            float amp = __ldg(xp), ph = __ldg(xp + 1);
            s_amp[tid] = amp;
            float sv, cv; sincosf(ph, &sv, &cv);
            s_sin[tid] = sv; s_cos[tid] = cv;
        }
        __syncthreads();

        // ---- GEMM1: 10 warps = 5 cg (8 cols) x 2 kh; lane halves split k ----
        {
            int cg = wid % 5, kh = wid / 5;
            int r = lane & 15, sub = lane >> 4;
            int kqq = kh * 2 + sub;       // k quarter 0..3
            float a0 = 0.f, a1 = 0.f, a2 = 0.f, a3 = 0.f;
            float a4 = 0.f, a5 = 0.f, a6 = 0.f, a7 = 0.f;
            const float* wp = W1s + cg * 8;
            #pragma unroll 4
            for (int mm = 0; mm < 16; ++mm) {
                int m = kqq * 16 + mm;
                float4 hv = *(const float4*)&h4s[(m * 16 + r) * 4];
                #pragma unroll
                for (int d = 0; d < 4; ++d) {
                    float hk = (d == 0) ? hv.x : (d == 1) ? hv.y : (d == 2) ? hv.z : hv.w;
                    float4 w0 = *(const float4*)&wp[(4 * m + d) * 40];
                    float4 w1 = *(const float4*)&wp[(4 * m + d) * 40 + 4];
                    a0 += hk * w0.x; a1 += hk * w0.y; a2 += hk * w0.z; a3 += hk * w0.w;
                    a4 += hk * w1.x; a5 += hk * w1.y; a6 += hk * w1.z; a7 += hk * w1.w;
                }
            }
            a0 += __shfl_down_sync(0xffffffffu, a0, 16);
            a1 += __shfl_down_sync(0xffffffffu, a1, 16);
            a2 += __shfl_down_sync(0xffffffffu, a2, 16);
            a3 += __shfl_down_sync(0xffffffffu, a3, 16);
            a4 += __shfl_down_sync(0xffffffffu, a4, 16);
            a5 += __shfl_down_sync(0xffffffffu, a5, 16);
            a6 += __shfl_down_sync(0xffffffffu, a6, 16);
            a7 += __shfl_down_sync(0xffffffffu, a7, 16);
            if (sub == 0) {
                float* s = S1 + kh * 680 + (cg * 8) * 17 + r;
                s[0]   = a0; s[17]  = a1; s[34]  = a2; s[51]  = a3;
                s[68]  = a4; s[85]  = a5; s[102] = a6; s[119] = a7;
            }
        }
        __syncthreads();

        // ---- epilogue 1: a, p1, p2 -> u (128 threads: 16 rows x 8 cols) ----
        if (tid < 128) {
            int jj = tid & 7, r = tid >> 3;
            float sa  = S1[(0  + jj) * 17 + r] + S1[680 + (0  + jj) * 17 + r];
            float sp1 = S1[(8  + jj) * 17 + r] + S1[680 + (8  + jj) * 17 + r];
            float sp2 = S1[(16 + jj) * 17 + r] + S1[680 + (16 + jj) * 17 + r];
            float a  = fast_tanh(sa  + s_amp[r] * s_w0[jj]      + s_b1[jj]);
            float p1 = fast_tanh(sp1 + s_cos[r] * s_w0[8 + jj]  + s_b1[8 + jj]);
            float p2 = fast_tanh(sp2 + s_sin[r] * s_w0[16 + jj] + s_b1[16 + jj]);
            g_u[(r0 + r) * HH + j0 + jj] =
                a * p1 * p2 * (1.f - a) * (1.f - p1) * (1.f - p2);
        }
        group_bar(fl, nj, base, ++ep);

        // ---- stage 2: load u tile ----
        for (int idx = tid; idx < 16 * 64; idx += NT) {
            int r = idx >> 6, kc = idx & 63;
            float4 v = ldcg4((const float4*)(g_u + (r0 + r) * HH) + kc);
            *(float4*)&u4s[(kc * 16 + r) * 4] = v;
        }
        __syncthreads();

        // ---- GEMM2: warps 0-7 = 2 cg2 (8 cols) x 4 ke; lane halves split k ----
        if (wid < 8) {
            int cg2 = wid & 1, ke = wid >> 1;
            int r = lane & 15, sub = lane >> 4;
            int keight = ke * 2 + sub;    // k eighth 0..7
            float a0 = 0.f, a1 = 0.f, a2 = 0.f, a3 = 0.f;
            float a4 = 0.f, a5 = 0.f, a6 = 0.f, a7 = 0.f;
            const float* wp = W2s + cg2 * 8;
            #pragma unroll 4
            for (int mm = 0; mm < 8; ++mm) {
                int m = keight * 8 + mm;
                float4 uv = *(const float4*)&u4s[(m * 16 + r) * 4];
                #pragma unroll
                for (int d = 0; d < 4; ++d) {
                    float uk = (d == 0) ? uv.x : (d == 1) ? uv.y : (d == 2) ? uv.z : uv.w;
                    float4 w0 = *(const float4*)&wp[(4 * m + d) * 16];
                    float4 w1 = *(const float4*)&wp[(4 * m + d) * 16 + 4];
                    a0 += uk * w0.x; a1 += uk * w0.y; a2 += uk * w0.z; a3 += uk * w0.w;
                    a4 += uk * w1.x; a5 += uk * w1.y; a6 += uk * w1.z; a7 += uk * w1.w;
                }
            }
            a0 += __shfl_down_sync(0xffffffffu, a0, 16);
            a1 += __shfl_down_sync(0xffffffffu, a1, 16);
            a2 += __shfl_down_sync(0xffffffffu, a2, 16);
            a3 += __shfl_down_sync(0xffffffffu, a3, 16);
            a4 += __shfl_down_sync(0xffffffffu, a4, 16);
            a5 += __shfl_down_sync(0xffffffffu, a5, 16);
            a6 += __shfl_down_sync(0xffffffffu, a6, 16);
            a7 += __shfl_down_sync(0xffffffffu, a7, 16);
            if (sub == 0) {
                float* s = S2 + ke * 272 + (cg2 * 8) * 17 + r;
                s[0]   = a0; s[17]  = a1; s[34]  = a2; s[51]  = a3;
                s[68]  = a4; s[85]  = a5; s[102] = a6; s[119] = a7;
            }
        } else if (nj == 0 && t >= 1) {
            // warps 8,9: output row t-1 from h4s (= h(t-1)), 16 rows
            #pragma unroll
            for (int it = 0; it < 2; ++it) {
                int item = it * 64 + (wid - 8) * 32 + lane;   // 0..127
                int r = item >> 3, kk = item & 7;
                float o0 = 0.f, o1 = 0.f;
                for (int k = kk * 32; k < kk * 32 + 32; ++k) {
                    float v = h4s[(k >> 2) * 64 + r * 4 + (k & 3)];
                    o0 += v * s_Wo[k * 2];
                    o1 += v * s_Wo[k * 2 + 1];
                }
                o0 += __shfl_xor_sync(0xffffffffu, o0, 1);
                o0 += __shfl_xor_sync(0xffffffffu, o0, 2);
                o0 += __shfl_xor_sync(0xffffffffu, o0, 4);
                o1 += __shfl_xor_sync(0xffffffffu, o1, 1);
                o1 += __shfl_xor_sync(0xffffffffu, o1, 2);
                o1 += __shfl_xor_sync(0xffffffffu, o1, 4);
                if (kk == 0) {
                    float* op = out + (((r0 + r) * TT) + (t - 1)) * 2;
                    op[0] = o0 + s_bo[0];
                    op[1] = o1 + s_bo[1];
                }
            }
        }
        __syncthreads();

        // ---- epilogue 2: z, h_cand, h_new (128 threads) ----
        if (tid < 128) {
            int jj = tid & 7, r = tid >> 3;
            int j = j0 + jj;
            float zp = s_bz[jj], hp = s_bh[jj];
            #pragma unroll
            for (int e = 0; e < 4; ++e) {
                zp += S2[e * 272 + jj * 17 + r];
                hp += S2[e * 272 + (8 + jj) * 17 + r];
            }
            zp += S1[(24 + jj) * 17 + r] + S1[680 + (24 + jj) * 17 + r];
            hp += S1[(32 + jj) * 17 + r] + S1[680 + (32 + jj) * 17 + r];
            float z  = fast_sigmoid(zp);
            float hc = fast_tanh(hp);
            float hold = h4s[(j >> 2) * 64 + r * 4 + (j & 3)];
            float hn = z * hold + (1.f - z) * hc;
            g_h[(r0 + r) * HH + j] = hn;
            if (t == TT - 1)
                out[BB * TT * 2 + (r0 + r) * HH + j] = hn;
        }
        group_bar(fl, nj, base, ++ep);
    }

    // ---- final output row t=1023 from g_h (after final barrier) ----
    if (nj == 0 && tid < 128) {
        int r = tid >> 3, kk = tid & 7;
        float o0 = 0.f, o1 = 0.f;
        for (int k = kk * 32; k < kk * 32 + 32; ++k) {
            float v = ldcg1(&g_h[(r0 + r) * HH + k]);
            o0 += v * s_Wo[k * 2];
            o1 += v * s_Wo[k * 2 + 1];
        }
        o0 += __shfl_xor_sync(0xffffffffu, o0, 1);
        o0 += __shfl_xor_sync(0xffffffffu, o0, 2);
        o0 += __shfl_xor_sync(0xffffffffu, o0, 4);
        o1 += __shfl_xor_sync(0xffffffffu, o1, 1);
        o1 += __shfl_xor_sync(0xffffffffu, o1, 2);
        o1 += __shfl_xor_sync(0xffffffffu, o1, 4);
        if (kk == 0) {
            float* op = out + (((r0 + r) * TT) + (TT - 1)) * 2;
            op[0] = o0 + s_bo[0];
            op[1] = o1 + s_bo[1];
        }
    }
}

extern "C" void kernel_launch(void* const* d_in, const int* in_sizes, int n_in,
                              void* d_out, int out_size) {
    const float* x   = (const float*)d_in[0];
    const float* h0  = (const float*)d_in[1];
    const float* Wa  = (const float*)d_in[2];
    const float* ba  = (const float*)d_in[3];
    const float* Wp1 = (const float*)d_in[4];
    const float* bp1 = (const float*)d_in[5];
    const float* Wp2 = (const float*)d_in[6];
    const float* bp2 = (const float*)d_in[7];
    const float* Wz  = (const float*)d_in[8];
    const float* bz  = (const float*)d_in[9];
    const float* Wh  = (const float*)d_in[10];
    const float* bh  = (const float*)d_in[11];
    const float* Wo  = (const float*)d_in[12];
    const float* bo  = (const float*)d_in[13];
    float* out = (float*)d_out;

    cudaFuncSetAttribute(pgjanet_kernel,
                         cudaFuncAttributeMaxDynamicSharedMemorySize, SMEM_BYTES);
    pgjanet_kernel<<<NCTA, NT, SMEM_BYTES>>>(
        x, h0, Wa, ba, Wp1, bp1, Wp2, bp2, Wz, bz, Wh, bh, Wo, bo, out);
}